// round 2
// baseline (speedup 1.0000x reference)
#include <cuda_runtime.h>
#include <math.h>

// Problem shape (fixed by the dataset)
#define BATCH 8
#define TQn   2048
#define TKn   2048
#define DIMn  1024
#define DVn   1024

// Scratch: un-normalized weights W[b,q,k] = exp(tanh(q.k + bias_k)), and 1/rowsum.
__device__ float g_W[(size_t)BATCH * TQn * TKn];     // 128 MiB
__device__ float g_rinv[BATCH * TQn];

// ---------------------------------------------------------------------------
// Kernel 1: W = exp(tanh(Q @ K + bias))
//   Q: [B, TQ, DIM] row-major, K: [B, DIM, TK] row-major (already GEMM-friendly)
// Classic register-blocked SGEMM: BM=BN=128, BK=16, 256 threads, 8x8 microtile.
// ---------------------------------------------------------------------------
__global__ __launch_bounds__(256, 2)
void qk_kernel(const float* __restrict__ Q, const float* __restrict__ Km,
               const float* __restrict__ bias)
{
    constexpr int BM = 128, BN = 128, BK = 16, TM = 8, TN = 8;

    const int b        = blockIdx.z;
    const int blockRow = blockIdx.y * BM;
    const int blockCol = blockIdx.x * BN;

    __shared__ float As[BK][BM];   // transposed Q tile
    __shared__ float Bs[BK][BN];   // K tile (natural layout)

    const float* Qb = Q  + (size_t)b * TQn * DIMn;
    const float* Kb = Km + (size_t)b * DIMn * TKn;

    const int tid = threadIdx.x;
    const int tx  = tid % (BN / TN);   // 0..15
    const int ty  = tid / (BN / TN);   // 0..15

    float acc[TM][TN] = {};

    for (int t = 0; t < DIMn; t += BK) {
        // Cooperative loads: 512 float4 each for A and B, 2 per thread each.
        #pragma unroll
        for (int i = 0; i < 2; i++) {
            const int idx = tid + i * 256;
            // A tile: 128 rows x 16 cols, transpose into As[k][m]
            const int ar = idx / (BK / 4);
            const int ac = (idx % (BK / 4)) * 4;
            float4 av = *reinterpret_cast<const float4*>(
                Qb + (size_t)(blockRow + ar) * DIMn + t + ac);
            As[ac + 0][ar] = av.x;
            As[ac + 1][ar] = av.y;
            As[ac + 2][ar] = av.z;
            As[ac + 3][ar] = av.w;
            // B tile: 16 rows x 128 cols, direct copy
            const int br = idx / (BN / 4);
            const int bc = (idx % (BN / 4)) * 4;
            *reinterpret_cast<float4*>(&Bs[br][bc]) =
                *reinterpret_cast<const float4*>(
                    Kb + (size_t)(t + br) * TKn + blockCol + bc);
        }
        __syncthreads();

        #pragma unroll
        for (int kk = 0; kk < BK; kk++) {
            float ra[TM], rb[TN];
            float4 a0 = *reinterpret_cast<const float4*>(&As[kk][ty * TM]);
            float4 a1 = *reinterpret_cast<const float4*>(&As[kk][ty * TM + 4]);
            ra[0]=a0.x; ra[1]=a0.y; ra[2]=a0.z; ra[3]=a0.w;
            ra[4]=a1.x; ra[5]=a1.y; ra[6]=a1.z; ra[7]=a1.w;
            float4 b0 = *reinterpret_cast<const float4*>(&Bs[kk][tx * TN]);
            float4 b1 = *reinterpret_cast<const float4*>(&Bs[kk][tx * TN + 4]);
            rb[0]=b0.x; rb[1]=b0.y; rb[2]=b0.z; rb[3]=b0.w;
            rb[4]=b1.x; rb[5]=b1.y; rb[6]=b1.z; rb[7]=b1.w;
            #pragma unroll
            for (int m = 0; m < TM; m++)
                #pragma unroll
                for (int n = 0; n < TN; n++)
                    acc[m][n] = fmaf(ra[m], rb[n], acc[m][n]);
        }
        __syncthreads();
    }

    // Epilogue: w = exp(tanh(score + bias[k]))
    float* Wb = g_W + (size_t)b * TQn * TKn;
    float bv[TN];
    #pragma unroll
    for (int n = 0; n < TN; n++) bv[n] = bias[blockCol + tx * TN + n];

    #pragma unroll
    for (int m = 0; m < TM; m++) {
        const int row = blockRow + ty * TM + m;
        float* wrow = Wb + (size_t)row * TKn + blockCol + tx * TN;
        #pragma unroll
        for (int n = 0; n < TN; n += 4) {
            float4 w;
            w.x = __expf(tanhf(acc[m][n + 0] + bv[n + 0]));
            w.y = __expf(tanhf(acc[m][n + 1] + bv[n + 1]));
            w.z = __expf(tanhf(acc[m][n + 2] + bv[n + 2]));
            w.w = __expf(tanhf(acc[m][n + 3] + bv[n + 3]));
            *reinterpret_cast<float4*>(wrow + n) = w;
        }
    }
}

// ---------------------------------------------------------------------------
// Kernel 2: deterministic per-row reduction -> reciprocal rowsum
// One warp per (b, q) row; fixed strided order + fixed shuffle tree.
// ---------------------------------------------------------------------------
__global__ __launch_bounds__(256)
void rowsum_kernel()
{
    const int warp = (blockIdx.x * blockDim.x + threadIdx.x) >> 5;
    const int lane = threadIdx.x & 31;
    if (warp >= BATCH * TQn) return;

    const float* row = g_W + (size_t)warp * TKn;
    float s = 0.0f;
    #pragma unroll 4
    for (int j = lane; j < TKn; j += 32) s += row[j];
    #pragma unroll
    for (int o = 16; o > 0; o >>= 1) s += __shfl_xor_sync(0xffffffffu, s, o);
    if (lane == 0) g_rinv[warp] = 1.0f / s;
}

// ---------------------------------------------------------------------------
// Kernel 3: O = (W @ V) * rinv
//   W: [B, TQ, TK] row-major (scratch), V: [B, TK, DV] row-major
// Same SGEMM skeleton as kernel 1.
// ---------------------------------------------------------------------------
__global__ __launch_bounds__(256, 2)
void pv_kernel(const float* __restrict__ V, float* __restrict__ Out)
{
    constexpr int BM = 128, BN = 128, BK = 16, TM = 8, TN = 8;

    const int b        = blockIdx.z;
    const int blockRow = blockIdx.y * BM;
    const int blockCol = blockIdx.x * BN;

    __shared__ float As[BK][BM];
    __shared__ float Bs[BK][BN];

    const float* Wb = g_W + (size_t)b * TQn * TKn;
    const float* Vb = V   + (size_t)b * TKn * DVn;

    const int tid = threadIdx.x;
    const int tx  = tid % (BN / TN);
    const int ty  = tid / (BN / TN);

    float acc[TM][TN] = {};

    for (int t = 0; t < TKn; t += BK) {
        #pragma unroll
        for (int i = 0; i < 2; i++) {
            const int idx = tid + i * 256;
            const int ar = idx / (BK / 4);
            const int ac = (idx % (BK / 4)) * 4;
            float4 av = *reinterpret_cast<const float4*>(
                Wb + (size_t)(blockRow + ar) * TKn + t + ac);
            As[ac + 0][ar] = av.x;
            As[ac + 1][ar] = av.y;
            As[ac + 2][ar] = av.z;
            As[ac + 3][ar] = av.w;
            const int br = idx / (BN / 4);
            const int bc = (idx % (BN / 4)) * 4;
            *reinterpret_cast<float4*>(&Bs[br][bc]) =
                *reinterpret_cast<const float4*>(
                    Vb + (size_t)(t + br) * DVn + blockCol + bc);
        }
        __syncthreads();

        #pragma unroll
        for (int kk = 0; kk < BK; kk++) {
            float ra[TM], rb[TN];
            float4 a0 = *reinterpret_cast<const float4*>(&As[kk][ty * TM]);
            float4 a1 = *reinterpret_cast<const float4*>(&As[kk][ty * TM + 4]);
            ra[0]=a0.x; ra[1]=a0.y; ra[2]=a0.z; ra[3]=a0.w;
            ra[4]=a1.x; ra[5]=a1.y; ra[6]=a1.z; ra[7]=a1.w;
            float4 b0 = *reinterpret_cast<const float4*>(&Bs[kk][tx * TN]);
            float4 b1 = *reinterpret_cast<const float4*>(&Bs[kk][tx * TN + 4]);
            rb[0]=b0.x; rb[1]=b0.y; rb[2]=b0.z; rb[3]=b0.w;
            rb[4]=b1.x; rb[5]=b1.y; rb[6]=b1.z; rb[7]=b1.w;
            #pragma unroll
            for (int m = 0; m < TM; m++)
                #pragma unroll
                for (int n = 0; n < TN; n++)
                    acc[m][n] = fmaf(ra[m], rb[n], acc[m][n]);
        }
        __syncthreads();
    }

    float* Ob = Out + (size_t)b * TQn * DVn;
    #pragma unroll
    for (int m = 0; m < TM; m++) {
        const int row = blockRow + ty * TM + m;
        const float r = g_rinv[b * TQn + row];
        float* orow = Ob + (size_t)row * DVn + blockCol + tx * TN;
        #pragma unroll
        for (int n = 0; n < TN; n += 4) {
            float4 o;
            o.x = acc[m][n + 0] * r;
            o.y = acc[m][n + 1] * r;
            o.z = acc[m][n + 2] * r;
            o.w = acc[m][n + 3] * r;
            *reinterpret_cast<float4*>(orow + n) = o;
        }
    }
}

// ---------------------------------------------------------------------------
extern "C" void kernel_launch(void* const* d_in, const int* in_sizes, int n_in,
                              void* d_out, int out_size)
{
    const float* q    = (const float*)d_in[0];   // [B, TQ, D]
    const float* k    = (const float*)d_in[1];   // [B, D, TK]
    const float* v    = (const float*)d_in[2];   // [B, TK, DV]
    const float* bias = (const float*)d_in[3];   // [TK]
    float* out = (float*)d_out;                  // [B, TQ, DV]

    (void)in_sizes; (void)n_in; (void)out_size;

    // Kernel 1: scores -> un-normalized weights
    {
        dim3 grid(TKn / 128, TQn / 128, BATCH);
        qk_kernel<<<grid, 256>>>(q, k, bias);
    }
    // Kernel 2: reciprocal row sums (8 warps per block)
    {
        const int rows = BATCH * TQn;
        const int blocks = rows / 8;   // 8 warps per 256-thread block
        rowsum_kernel<<<blocks, 256>>>();
    }
    // Kernel 3: weighted sum of values, normalized
    {
        dim3 grid(DVn / 128, TQn / 128, BATCH);
        pv_kernel<<<grid, 256>>>(v, out);
    }
}

// round 5
// speedup vs baseline: 3.0379x; 3.0379x over previous
#include <cuda_runtime.h>
#include <cuda_bf16.h>
#include <cstdint>
#include <math.h>

#define BATCH 8
#define TQn   2048
#define TKn   2048
#define DIMn  1024
#define DVn   1024

// ---------------- scratch (device globals; no allocation) ----------------
__device__ __nv_bfloat16 g_Qhi [(size_t)BATCH * TQn * DIMn];
__device__ __nv_bfloat16 g_Qlo [(size_t)BATCH * TQn * DIMn];
__device__ __nv_bfloat16 g_KThi[(size_t)BATCH * TKn * DIMn];   // K^T: [B, TK, D]
__device__ __nv_bfloat16 g_KTlo[(size_t)BATCH * TKn * DIMn];
__device__ __nv_bfloat16 g_VThi[(size_t)BATCH * DVn * TKn];    // V^T: [B, DV, TK]
__device__ __nv_bfloat16 g_VTlo[(size_t)BATCH * DVn * TKn];
__device__ __nv_bfloat16 g_Whi [(size_t)BATCH * TQn * TKn];
__device__ __nv_bfloat16 g_Wlo [(size_t)BATCH * TQn * TKn];
__device__ float         g_rinv[BATCH * TQn];

// ---------------- helpers ----------------
__device__ __forceinline__ uint32_t smem_u32(const void* p) {
    uint32_t a;
    asm("{ .reg .u64 t; cvta.to.shared.u64 t, %1; cvt.u32.u64 %0, t; }" : "=r"(a) : "l"(p));
    return a;
}

#define SW128X(x) ((x) ^ (((x) >> 3) & 0x70))

__device__ __forceinline__ void ldsm4(uint32_t* r, uint32_t a) {
    asm volatile("ldmatrix.sync.aligned.m8n8.x4.shared.b16 {%0,%1,%2,%3}, [%4];"
                 : "=r"(r[0]), "=r"(r[1]), "=r"(r[2]), "=r"(r[3]) : "r"(a));
}

__device__ __forceinline__ void mma_bf16(float* c, const uint32_t* a, const uint32_t* b) {
    asm volatile(
        "mma.sync.aligned.m16n8k16.row.col.f32.bf16.bf16.f32 "
        "{%0,%1,%2,%3}, {%4,%5,%6,%7}, {%8,%9}, {%0,%1,%2,%3};"
        : "+f"(c[0]), "+f"(c[1]), "+f"(c[2]), "+f"(c[3])
        : "r"(a[0]), "r"(a[1]), "r"(a[2]), "r"(a[3]), "r"(b[0]), "r"(b[1]));
}

__device__ __forceinline__ void cp16(uint32_t dst, const void* src) {
    asm volatile("cp.async.cg.shared.global [%0], [%1], 16;" :: "r"(dst), "l"(src));
}

// Copy one 128x64 bf16 tile (row-major, leading dim `ld`) into SW128 smem.
__device__ __forceinline__ void cp_tile_async(uint32_t dst, const __nv_bfloat16* __restrict__ src,
                                              int ld) {
    const int tid = threadIdx.x;
    #pragma unroll
    for (int i = 0; i < 4; i++) {
        const int idx = tid + i * 256;          // 0..1023
        const int row = idx >> 3;
        const int c8  = (idx & 7) << 3;         // bf16 col, step 8 (16B)
        const uint32_t bo = (uint32_t)(row * 128 + c8 * 2);
        cp16(dst + SW128X(bo), src + (size_t)row * ld + c8);
    }
}

// ---------------- Phase 0a: Q -> bf16 hi/lo ----------------
__global__ __launch_bounds__(256)
void convert_q_kernel(const float4* __restrict__ in) {
    const int i = blockIdx.x * 256 + threadIdx.x;
    float4 v = in[i];
    __nv_bfloat16 h0 = __float2bfloat16(v.x), h1 = __float2bfloat16(v.y);
    __nv_bfloat16 h2 = __float2bfloat16(v.z), h3 = __float2bfloat16(v.w);
    __nv_bfloat16 l0 = __float2bfloat16(v.x - __bfloat162float(h0));
    __nv_bfloat16 l1 = __float2bfloat16(v.y - __bfloat162float(h1));
    __nv_bfloat16 l2 = __float2bfloat16(v.z - __bfloat162float(h2));
    __nv_bfloat16 l3 = __float2bfloat16(v.w - __bfloat162float(h3));
    __nv_bfloat162* oh = reinterpret_cast<__nv_bfloat162*>(g_Qhi);
    __nv_bfloat162* ol = reinterpret_cast<__nv_bfloat162*>(g_Qlo);
    oh[2 * i]     = __halves2bfloat162(h0, h1);
    oh[2 * i + 1] = __halves2bfloat162(h2, h3);
    ol[2 * i]     = __halves2bfloat162(l0, l1);
    ol[2 * i + 1] = __halves2bfloat162(l2, l3);
}

// ---------------- Phase 0b: transpose + convert (K and V) ----------------
// in: [B, R, C] f32 -> out[hi/lo]: [B, C, R] bf16.  SEL 0 = K, 1 = V.
template<int SEL>
__global__ __launch_bounds__(256)
void transpose_convert_kernel(const float* __restrict__ in, int R, int C) {
    __shared__ float t[32][33];
    const int b  = blockIdx.z;
    const int c0 = blockIdx.x * 32;
    const int r0 = blockIdx.y * 32;
    const int tx = threadIdx.x & 31;
    const int ty = threadIdx.x >> 5;
    const float* inb = in + (size_t)b * R * C;
    #pragma unroll
    for (int j = 0; j < 4; j++)
        t[ty + j * 8][tx] = inb[(size_t)(r0 + ty + j * 8) * C + c0 + tx];
    __syncthreads();
    __nv_bfloat16* oh = (SEL == 0 ? g_KThi : g_VThi) + (size_t)b * R * C;
    __nv_bfloat16* ol = (SEL == 0 ? g_KTlo : g_VTlo) + (size_t)b * R * C;
    #pragma unroll
    for (int j = 0; j < 4; j++) {
        float v = t[tx][ty + j * 8];
        __nv_bfloat16 h = __float2bfloat16(v);
        __nv_bfloat16 l = __float2bfloat16(v - __bfloat162float(h));
        size_t o = (size_t)(c0 + ty + j * 8) * R + r0 + tx;
        oh[o] = h;
        ol[o] = l;
    }
}

// ---------------- Phase 1/3: HMMA split-bf16 GEMM ----------------
// C(128x128) = (Ahi+Alo) @ (Bhi+Blo)^T over KDIM, split-3 terms.
// A: [2048 x KDIM] hi/lo rows at bRow; B: [N x KDIM] hi/lo rows at bCol.
// IS_QK: epilogue exp(tanh(acc + bias[col])) -> Whi/Wlo.
// else:  epilogue acc * rinv[row] -> Out f32.
template<int KDIM, bool IS_QK>
__global__ __launch_bounds__(256, 1)
void hmma_gemm_kernel(const float* __restrict__ bias, float* __restrict__ Out) {
    constexpr int NK = KDIM / 64;

    extern __shared__ char dsm[];
    const uint32_t raw  = smem_u32(dsm);
    const uint32_t base = (raw + 1023) & ~1023u;
    char* bp = dsm + (base - raw);
    float* auxS = reinterpret_cast<float*>(bp + 131072);   // bias (QK) or rinv (PV)

    const int tid  = threadIdx.x;
    const int lane = tid & 31;
    const int wid  = tid >> 5;
    const int wm   = wid & 1;      // 2 warps along M
    const int wn   = wid >> 1;     // 4 warps along N
    const int b    = blockIdx.z;
    const int bRow = blockIdx.y * 128;
    const int bCol = blockIdx.x * 128;

    const __nv_bfloat16* Ah = (IS_QK ? g_Qhi  : g_Whi ) + (size_t)b * 2048 * KDIM + (size_t)bRow * KDIM;
    const __nv_bfloat16* Al = (IS_QK ? g_Qlo  : g_Wlo ) + (size_t)b * 2048 * KDIM + (size_t)bRow * KDIM;
    const int b_rows = IS_QK ? TKn : DVn;
    const __nv_bfloat16* Bh = (IS_QK ? g_KThi : g_VThi) + (size_t)b * b_rows * KDIM + (size_t)bCol * KDIM;
    const __nv_bfloat16* Bl = (IS_QK ? g_KTlo : g_VTlo) + (size_t)b * b_rows * KDIM + (size_t)bCol * KDIM;

    if (tid < 128)
        auxS[tid] = IS_QK ? bias[bCol + tid] : g_rinv[b * TQn + bRow + tid];

    float acc[4][4][4] = {};

    // prologue: stage 0
    {
        const uint32_t dst = base;
        cp_tile_async(dst,         Ah, KDIM);
        cp_tile_async(dst + 16384, Al, KDIM);
        cp_tile_async(dst + 32768, Bh, KDIM);
        cp_tile_async(dst + 49152, Bl, KDIM);
        asm volatile("cp.async.commit_group;" ::: "memory");
    }

    // per-thread ldmatrix geometry
    const int a_row  = wm * 64 + (lane & 15);
    const int a_csel = lane >> 4;                       // 0/1
    const int b_row  = wn * 32 + (lane & 7) + ((lane & 16) >> 1);
    const int b_csel = (lane >> 3) & 1;

    for (int it = 0; it < NK; ++it) {
        if (it + 1 < NK) {
            const int koff = (it + 1) * 64;
            const uint32_t dst = base + (uint32_t)(((it + 1) & 1) * 65536);
            cp_tile_async(dst,         Ah + koff, KDIM);
            cp_tile_async(dst + 16384, Al + koff, KDIM);
            cp_tile_async(dst + 32768, Bh + koff, KDIM);
            cp_tile_async(dst + 49152, Bl + koff, KDIM);
            asm volatile("cp.async.commit_group;" ::: "memory");
            asm volatile("cp.async.wait_group 1;" ::: "memory");
        } else {
            asm volatile("cp.async.wait_group 0;" ::: "memory");
        }
        __syncthreads();

        const uint32_t st = base + (uint32_t)((it & 1) * 65536);
        #pragma unroll
        for (int s = 0; s < 4; s++) {
            uint32_t ah[4][4], al[4][4], bh[4][2], bl[4][2];
            const int ac = 2 * s + a_csel;
            #pragma unroll
            for (int i = 0; i < 4; i++) {
                const uint32_t bo = (uint32_t)((a_row + i * 16) * 128 + ac * 16);
                ldsm4(ah[i], st + SW128X(bo));
                ldsm4(al[i], st + 16384 + SW128X(bo));
            }
            const int bc = 2 * s + b_csel;
            #pragma unroll
            for (int jp = 0; jp < 2; jp++) {
                const uint32_t bo = (uint32_t)((b_row + jp * 16) * 128 + bc * 16);
                uint32_t r[4];
                ldsm4(r, st + 32768 + SW128X(bo));
                bh[2 * jp][0] = r[0]; bh[2 * jp][1] = r[1];
                bh[2 * jp + 1][0] = r[2]; bh[2 * jp + 1][1] = r[3];
                ldsm4(r, st + 49152 + SW128X(bo));
                bl[2 * jp][0] = r[0]; bl[2 * jp][1] = r[1];
                bl[2 * jp + 1][0] = r[2]; bl[2 * jp + 1][1] = r[3];
            }
            #pragma unroll
            for (int i = 0; i < 4; i++)
                #pragma unroll
                for (int j = 0; j < 4; j++) {
                    mma_bf16(acc[i][j], ah[i], bh[j]);
                    mma_bf16(acc[i][j], ah[i], bl[j]);
                    mma_bf16(acc[i][j], al[i], bh[j]);
                }
        }
        __syncthreads();
    }

    // ---------------- epilogue ----------------
    if (IS_QK) {
        const size_t Wbase = (size_t)b * TQn * TKn;
        #pragma unroll
        for (int i = 0; i < 4; i++) {
            const int r0 = wm * 64 + i * 16 + (lane >> 2);
            #pragma unroll
            for (int half = 0; half < 2; half++) {
                const int r = r0 + half * 8;
                const size_t rowoff = Wbase + (size_t)(bRow + r) * TKn + bCol;
                #pragma unroll
                for (int j = 0; j < 4; j++) {
                    const int col = wn * 32 + j * 8 + (lane & 3) * 2;
                    float w0 = __expf(tanhf(acc[i][j][half * 2 + 0] + auxS[col]));
                    float w1 = __expf(tanhf(acc[i][j][half * 2 + 1] + auxS[col + 1]));
                    __nv_bfloat16 h0 = __float2bfloat16(w0);
                    __nv_bfloat16 h1 = __float2bfloat16(w1);
                    __nv_bfloat16 l0 = __float2bfloat16(w0 - __bfloat162float(h0));
                    __nv_bfloat16 l1 = __float2bfloat16(w1 - __bfloat162float(h1));
                    *reinterpret_cast<__nv_bfloat162*>(g_Whi + rowoff + col) = __halves2bfloat162(h0, h1);
                    *reinterpret_cast<__nv_bfloat162*>(g_Wlo + rowoff + col) = __halves2bfloat162(l0, l1);
                }
            }
        }
    } else {
        const size_t Obase = (size_t)b * TQn * DVn;
        #pragma unroll
        for (int i = 0; i < 4; i++) {
            const int r0 = wm * 64 + i * 16 + (lane >> 2);
            #pragma unroll
            for (int half = 0; half < 2; half++) {
                const int r  = r0 + half * 8;
                const float rv = auxS[r];
                const size_t rowoff = Obase + (size_t)(bRow + r) * DVn + bCol;
                #pragma unroll
                for (int j = 0; j < 4; j++) {
                    const int col = wn * 32 + j * 8 + (lane & 3) * 2;
                    float2 o;
                    o.x = acc[i][j][half * 2 + 0] * rv;
                    o.y = acc[i][j][half * 2 + 1] * rv;
                    *reinterpret_cast<float2*>(Out + rowoff + col) = o;
                }
            }
        }
    }
}

// ---------------- Phase 2: deterministic rowsum -> 1/sum ----------------
__global__ __launch_bounds__(256)
void rowsum_kernel() {
    const int warp = (blockIdx.x * 256 + threadIdx.x) >> 5;
    const int lane = threadIdx.x & 31;
    if (warp >= BATCH * TQn) return;
    const uint4* h4 = reinterpret_cast<const uint4*>(g_Whi + (size_t)warp * TKn);
    const uint4* l4 = reinterpret_cast<const uint4*>(g_Wlo + (size_t)warp * TKn);
    float s = 0.0f;
    for (int j = lane; j < TKn / 8; j += 32) {
        uint4 hv = h4[j], lv = l4[j];
        uint32_t ha[4] = {hv.x, hv.y, hv.z, hv.w};
        uint32_t la[4] = {lv.x, lv.y, lv.z, lv.w};
        #pragma unroll
        for (int k = 0; k < 4; k++) {
            float2 fh = __bfloat1622float2(*reinterpret_cast<__nv_bfloat162*>(&ha[k]));
            float2 fl = __bfloat1622float2(*reinterpret_cast<__nv_bfloat162*>(&la[k]));
            s += fh.x + fh.y + fl.x + fl.y;
        }
    }
    #pragma unroll
    for (int o = 16; o > 0; o >>= 1) s += __shfl_xor_sync(0xffffffffu, s, o);
    if (lane == 0) g_rinv[warp] = 1.0f / s;
}

// ---------------- launch ----------------
extern "C" void kernel_launch(void* const* d_in, const int* in_sizes, int n_in,
                              void* d_out, int out_size) {
    const float* q    = (const float*)d_in[0];   // [B, TQ, D]
    const float* k    = (const float*)d_in[1];   // [B, D, TK]
    const float* v    = (const float*)d_in[2];   // [B, TK, DV]
    const float* bias = (const float*)d_in[3];   // [TK]
    float* out = (float*)d_out;
    (void)in_sizes; (void)n_in; (void)out_size;

    const int SMEM_BYTES = 131072 + 512 + 1024;
    cudaFuncSetAttribute(hmma_gemm_kernel<DIMn, true>,
                         cudaFuncAttributeMaxDynamicSharedMemorySize, SMEM_BYTES);
    cudaFuncSetAttribute(hmma_gemm_kernel<TKn, false>,
                         cudaFuncAttributeMaxDynamicSharedMemorySize, SMEM_BYTES);

    // Phase 0: conversions
    {
        const int n4 = BATCH * TQn * DIMn / 4;
        convert_q_kernel<<<n4 / 256, 256>>>((const float4*)q);
        dim3 gk(TKn / 32, DIMn / 32, BATCH);
        transpose_convert_kernel<0><<<gk, 256>>>(k, DIMn, TKn);
        dim3 gv(DVn / 32, TKn / 32, BATCH);
        transpose_convert_kernel<1><<<gv, 256>>>(v, TKn, DVn);
    }
    // Phase 1: W = exp(tanh(QK + bias))
    {
        dim3 grid(TKn / 128, TQn / 128, BATCH);
        hmma_gemm_kernel<DIMn, true><<<grid, 256, SMEM_BYTES>>>(bias, nullptr);
    }
    // Phase 2: row sums
    rowsum_kernel<<<BATCH * TQn / 8, 256>>>();
    // Phase 3: O = (W V) * rinv
    {
        dim3 grid(DVn / 128, TQn / 128, BATCH);
        hmma_gemm_kernel<TKn, false><<<grid, 256, SMEM_BYTES>>>(nullptr, out);
    }
}